// round 13
// baseline (speedup 1.0000x reference)
#include <cuda_runtime.h>
#include <cuda_fp16.h>
#include <cstdint>

#define NT        16384     // M / 32-row tiles
#define GRIDSZ    148
#define THREADS   512
#define KDIM      256
#define NDIM      256
#define LSE_OFF   44.0f
#define LOG2E     1.4426950408889634f
#define LN2       0.6931471805599453f

// ---- dynamic smem layout (bytes) ----
#define OFF_C     0                    // 256 fp32: (bias - subtract - 44) * log2e
#define OFF_PSUM  1024                 // 4 quarters x (4 x 32) fp32
#define OFF_G     3072                 // 4 quarters x 32 fp32
#define OFF_A     4096                 // 4 quarters x (32 x 256 fp16); holds x*log2e
#define OFF_B     69632                // 256 x 256 fp16 = 131072
#define SMEM_TOTAL 200704

__device__ __forceinline__ uint32_t cvta_smem(const void* p) {
    uint32_t a;
    asm("{ .reg .u64 t; cvta.to.shared.u64 t, %1; cvt.u32.u64 %0, t; }" : "=r"(a) : "l"(p));
    return a;
}
__device__ __forceinline__ float ex2f(float x) {
    float y; asm("ex2.approx.ftz.f32 %0, %1;" : "=f"(y) : "f"(x)); return y;
}
__device__ __forceinline__ float tanhfast(float x) {
    float y; asm("tanh.approx.f32 %0, %1;" : "=f"(y) : "f"(x)); return y;
}

// Swizzle<3,3,3>: row stride 512B (256 fp16). 16B-chunk index ^= row&7.
__device__ __forceinline__ uint32_t sw_off(int row, int col) {
    return (uint32_t)(row * 512 + (((col >> 3) ^ (row & 7)) << 4) + (col & 7) * 2);
}

#define LDSM_X4(r0, r1, r2, r3, addr) \
    asm volatile("ldmatrix.sync.aligned.m8n8.x4.shared.b16 {%0,%1,%2,%3}, [%4];" \
                 : "=r"(r0), "=r"(r1), "=r"(r2), "=r"(r3) : "r"(addr))

#define MMA16816(d, a, b0, b1) \
    asm volatile("mma.sync.aligned.m16n8k16.row.col.f32.f16.f16.f32 " \
                 "{%0,%1,%2,%3}, {%4,%5,%6,%7}, {%8,%9}, {%0,%1,%2,%3};" \
                 : "+f"((d)[0]), "+f"((d)[1]), "+f"((d)[2]), "+f"((d)[3]) \
                 : "r"((a)[0]), "r"((a)[1]), "r"((a)[2]), "r"((a)[3]), \
                   "r"(b0), "r"(b1))

// per-quarter named barrier (128 threads each; ids 1..4)
#define BARQ(id) asm volatile("bar.sync %0, 128;" :: "r"(id) : "memory")

__global__ void __launch_bounds__(THREADS, 1)
fused_gemm_lse_gelu_kernel(const float* __restrict__ x,
                           const float* __restrict__ w,
                           const float* __restrict__ bias,
                           const float* __restrict__ sub,
                           float* __restrict__ out) {
    extern __shared__ char sm[];
    const uint32_t sb = cvta_smem(sm);
    const int tid  = threadIdx.x;
    const int lane = tid & 31;
    const int q    = tid >> 7;          // quarter 0..3: independent 4-warp pipeline
    const int tidq = tid & 127;
    const int nw   = (tid >> 5) & 3;    // warp-in-quarter: N-group cols nw*64..+63
    const int barid = q + 1;

    float* csh   = (float*)(sm + OFF_C);
    float* psumQ = (float*)(sm + OFF_PSUM + q * 512);   // [4 groups][32 rows]
    float* gshQ  = (float*)(sm + OFF_G + q * 128);      // [32 rows]
    const uint32_t aQ = sb + OFF_A + (uint32_t)(q * 16384);

    // ---- stage W fp32 -> fp16 swizzled SMEM (whole CTA, resident forever) ----
    {
        const float4* wp = (const float4*)w;
#pragma unroll
        for (int i = 0; i < 32; i++) {
            int e = i * 2048 + tid * 4;
            float4 v = wp[i * 512 + tid];
            int n = e >> 8, k = e & 255;
            __half2 p0 = __floats2half2_rn(v.x, v.y);
            __half2 p1 = __floats2half2_rn(v.z, v.w);
            uint32_t addr = sb + OFF_B + sw_off(n, k);
            asm volatile("st.shared.v2.b32 [%0], {%1,%2};"
                         :: "r"(addr), "r"(*(uint32_t*)&p0), "r"(*(uint32_t*)&p1));
        }
    }
    if (tid < 256) csh[tid] = (bias[tid] - sub[tid] - LSE_OFF) * LOG2E;
    __syncthreads();   // B + csh visible; quarters never full-sync again

    const int t0 = 4 * blockIdx.x + q;

    // ---- per-quarter prologue: load, scale by log2e, convert, stage x(t0) ----
    uint32_t h2[32];
    {
        const float4* xp = (const float4*)(x + (size_t)t0 * (32 * KDIM));
#pragma unroll
        for (int i = 0; i < 16; i++) {
            float4 v = __ldcs(xp + i * 128 + tidq);
            __half2 a = __floats2half2_rn(v.x * LOG2E, v.y * LOG2E);
            __half2 b = __floats2half2_rn(v.z * LOG2E, v.w * LOG2E);
            h2[2 * i] = *(uint32_t*)&a;
            h2[2 * i + 1] = *(uint32_t*)&b;
        }
#pragma unroll
        for (int i = 0; i < 16; i++) {
            int e = i * 512 + tidq * 4;
            uint32_t addr = aQ + sw_off(e >> 8, e & 255);
            asm volatile("st.shared.v2.b32 [%0], {%1,%2};"
                         :: "r"(addr), "r"(h2[2 * i]), "r"(h2[2 * i + 1]));
        }
    }
    BARQ(barid);

    // ---- ldmatrix lane addresses (k-invariant parts) ----
    const int t4 = lane >> 3;
    const int a_row = (t4 & 1) * 8 + (lane & 7);
    const uint32_t a_kh = (uint32_t)(t4 >> 1);
    const int b_row0 = nw * 64 + (t4 >> 1) * 8 + (lane & 7);
    const uint32_t b_kh = (uint32_t)(t4 & 1);
    const uint32_t aBase0 = aQ + (uint32_t)(a_row * 512);
    const uint32_t aBase1 = aBase0 + 16 * 512;
    const uint32_t aRx = (uint32_t)(a_row & 7);
    uint32_t bBase[4], bRx[4];
#pragma unroll
    for (int ng = 0; ng < 4; ng++) {
        int br = b_row0 + ng * 16;
        bBase[ng] = sb + OFF_B + (uint32_t)(br * 512);
        bRx[ng] = (uint32_t)(br & 7);
    }

    for (int t = t0; t < NT; t += 4 * GRIDSZ) {
        // A(t) staged & visible (barrier at loop end / prologue)

        float acc[64];
#pragma unroll
        for (int i = 0; i < 64; i++) acc[i] = 0.0f;

        // ---- MMA mainloop: 16 k-steps of k16; warp = 32 rows x 64 cols ----
#pragma unroll
        for (int ks = 0; ks < 16; ks++) {
            const uint32_t kc = (uint32_t)(2 * ks);
            uint32_t a0[4], a1[4];
            LDSM_X4(a0[0], a0[1], a0[2], a0[3], aBase0 + (((kc + a_kh) ^ aRx) << 4));
            LDSM_X4(a1[0], a1[1], a1[2], a1[3], aBase1 + (((kc + a_kh) ^ aRx) << 4));
            uint32_t bf[4][4];
#pragma unroll
            for (int ng = 0; ng < 4; ng++)
                LDSM_X4(bf[ng][0], bf[ng][1], bf[ng][2], bf[ng][3],
                        bBase[ng] + (((kc + b_kh) ^ bRx[ng]) << 4));
#pragma unroll
            for (int ng = 0; ng < 4; ng++) {
                MMA16816(&acc[(ng * 2 + 0) * 4], a0, bf[ng][0], bf[ng][1]);
                MMA16816(&acc[(ng * 2 + 1) * 4], a0, bf[ng][2], bf[ng][3]);
                MMA16816(&acc[(8 + ng * 2 + 0) * 4], a1, bf[ng][0], bf[ng][1]);
                MMA16816(&acc[(8 + ng * 2 + 1) * 4], a1, bf[ng][2], bf[ng][3]);
            }
        }

        // ---- epilogue: base-2 LSE partial sums; acc already in log2e domain ----
        {
            const int n0 = nw * 64;
            float s4[4] = {0.0f, 0.0f, 0.0f, 0.0f};
#pragma unroll
            for (int nt = 0; nt < 8; nt++) {
                float c0 = csh[n0 + nt * 8 + (lane & 3) * 2];
                float c1 = csh[n0 + nt * 8 + (lane & 3) * 2 + 1];
#pragma unroll
                for (int mb = 0; mb < 2; mb++) {
                    const float* a = &acc[(mb * 8 + nt) * 4];
                    s4[2 * mb + 0] += ex2f(a[0] + c0) + ex2f(a[1] + c1);
                    s4[2 * mb + 1] += ex2f(a[2] + c0) + ex2f(a[3] + c1);
                }
            }
#pragma unroll
            for (int off = 1; off <= 2; off <<= 1) {
#pragma unroll
                for (int j = 0; j < 4; j++)
                    s4[j] += __shfl_xor_sync(0xFFFFFFFFu, s4[j], off);
            }
            if ((lane & 3) == 0) {
#pragma unroll
                for (int j = 0; j < 4; j++) {
                    int row = (j >> 1) * 16 + (j & 1) * 8 + (lane >> 2);
                    psumQ[nw * 32 + row] = s4[j];
                }
            }
        }
        BARQ(barid);   // psum visible; all LDSM of A(t) done

        // ---- combine -> lse -> gelu, distributed: warp nw does rows nw*8..+7 ----
        if (lane < 8) {
            int row = nw * 8 + lane;
            float S = psumQ[row] + psumQ[32 + row] + psumQ[64 + row] + psumQ[96 + row];
            float l = __logf(S) + LSE_OFF;
            float u = 0.7978845608028654f * (l + 0.044715f * l * l * l);
            gshQ[row] = 0.5f * l * (1.0f + tanhfast(u));
        }
        BARQ(barid);   // gsh visible

        // ---- store out(t) = gelu(lse) + x(t); h2 holds x*log2e -> fma by ln2 ----
        {
            float* op = out + (size_t)t * (32 * KDIM);
#pragma unroll
            for (int i = 0; i < 16; i++) {
                int e = i * 512 + tidq * 4;
                float gv = gshQ[e >> 8];
                __half2 p0 = *(__half2*)&h2[2 * i];
                __half2 p1 = *(__half2*)&h2[2 * i + 1];
                float4 o;
                o.x = fmaf(__low2float(p0),  LN2, gv);
                o.y = fmaf(__high2float(p0), LN2, gv);
                o.z = fmaf(__low2float(p1),  LN2, gv);
                o.w = fmaf(__high2float(p1), LN2, gv);
                __stcs((float4*)(op + e), o);
            }
        }

        // ---- load + convert x(t+1) into h2, then stage (R5-proven sequential tail) ----
        const int tn = t + 4 * GRIDSZ;
        if (tn < NT) {
            const float4* xp = (const float4*)(x + (size_t)tn * (32 * KDIM));
#pragma unroll
            for (int i = 0; i < 16; i++) {
                float4 v = __ldcs(xp + i * 128 + tidq);
                __half2 a = __floats2half2_rn(v.x * LOG2E, v.y * LOG2E);
                __half2 b = __floats2half2_rn(v.z * LOG2E, v.w * LOG2E);
                h2[2 * i] = *(uint32_t*)&a;
                h2[2 * i + 1] = *(uint32_t*)&b;
            }
#pragma unroll
            for (int i = 0; i < 16; i++) {
                int e = i * 512 + tidq * 4;
                uint32_t addr = aQ + sw_off(e >> 8, e & 255);
                asm volatile("st.shared.v2.b32 [%0], {%1,%2};"
                             :: "r"(addr), "r"(h2[2 * i]), "r"(h2[2 * i + 1]));
            }
        }
        BARQ(barid);   // A(t+1) visible for next MMA
    }
}

extern "C" void kernel_launch(void* const* d_in, const int* in_sizes, int n_in,
                              void* d_out, int out_size) {
    const float* x    = (const float*)d_in[0];
    const float* w    = (const float*)d_in[1];
    const float* bias = (const float*)d_in[2];
    const float* sub  = (const float*)d_in[3];
    float* out = (float*)d_out;

    cudaFuncSetAttribute(fused_gemm_lse_gelu_kernel,
                         cudaFuncAttributeMaxDynamicSharedMemorySize, SMEM_TOTAL);
    fused_gemm_lse_gelu_kernel<<<GRIDSZ, THREADS, SMEM_TOTAL>>>(x, w, bias, sub, out);
}

// round 14
// speedup vs baseline: 1.3475x; 1.3475x over previous
#include <cuda_runtime.h>
#include <cuda_fp16.h>
#include <cstdint>

#define NT        16384     // M / 32-row tiles
#define GRIDSZ    148
#define THREADS   512
#define KDIM      256
#define NDIM      256
#define LSE_OFF   44.0f

// ---- dynamic smem layout (bytes) ----
#define OFF_C     0                    // 256 fp32 (bias - subtract - LSE_OFF)
#define OFF_PSUM  1024                 // 4 quarters x (4 x 32) fp32
#define OFF_G     3072                 // 4 quarters x 32 fp32
#define OFF_A     4096                 // 4 quarters x (32 x 256 fp16 = 16384)
#define OFF_B     69632                // 256 x 256 fp16 = 131072
#define SMEM_TOTAL 200704

__device__ __forceinline__ uint32_t cvta_smem(const void* p) {
    uint32_t a;
    asm("{ .reg .u64 t; cvta.to.shared.u64 t, %1; cvt.u32.u64 %0, t; }" : "=r"(a) : "l"(p));
    return a;
}

// Swizzle<3,3,3>: row stride 512B (256 fp16). 16B-chunk index ^= row&7.
__device__ __forceinline__ uint32_t sw_off(int row, int col) {
    return (uint32_t)(row * 512 + (((col >> 3) ^ (row & 7)) << 4) + (col & 7) * 2);
}

#define LDSM_X4(r0, r1, r2, r3, addr) \
    asm volatile("ldmatrix.sync.aligned.m8n8.x4.shared.b16 {%0,%1,%2,%3}, [%4];" \
                 : "=r"(r0), "=r"(r1), "=r"(r2), "=r"(r3) : "r"(addr))

#define MMA16816(d, a, b0, b1) \
    asm volatile("mma.sync.aligned.m16n8k16.row.col.f32.f16.f16.f32 " \
                 "{%0,%1,%2,%3}, {%4,%5,%6,%7}, {%8,%9}, {%0,%1,%2,%3};" \
                 : "+f"((d)[0]), "+f"((d)[1]), "+f"((d)[2]), "+f"((d)[3]) \
                 : "r"((a)[0]), "r"((a)[1]), "r"((a)[2]), "r"((a)[3]), \
                   "r"(b0), "r"(b1))

// per-quarter named barrier (128 threads each; ids 1..4)
#define BARQ(id) asm volatile("bar.sync %0, 128;" :: "r"(id) : "memory")

__global__ void __launch_bounds__(THREADS, 1)
fused_gemm_lse_gelu_kernel(const float* __restrict__ x,
                           const float* __restrict__ w,
                           const float* __restrict__ bias,
                           const float* __restrict__ sub,
                           float* __restrict__ out) {
    extern __shared__ char sm[];
    const uint32_t sb = cvta_smem(sm);
    const int tid  = threadIdx.x;
    const int lane = tid & 31;
    const int q    = tid >> 7;          // quarter 0..3: independent 4-warp pipeline
    const int tidq = tid & 127;
    const int nw   = (tid >> 5) & 3;    // warp-in-quarter: N-group cols nw*64..+63
    const int barid = q + 1;

    float* csh   = (float*)(sm + OFF_C);
    float* psumQ = (float*)(sm + OFF_PSUM + q * 512);   // [4 groups][32 rows]
    float* gshQ  = (float*)(sm + OFF_G + q * 128);      // [32 rows]
    const uint32_t aQ = sb + OFF_A + (uint32_t)(q * 16384);

    // ---- stage W fp32 -> fp16 swizzled SMEM (whole CTA, resident forever) ----
    {
        const float4* wp = (const float4*)w;
#pragma unroll
        for (int i = 0; i < 32; i++) {
            int e = i * 2048 + tid * 4;
            float4 v = wp[i * 512 + tid];
            int n = e >> 8, k = e & 255;
            __half2 p0 = __floats2half2_rn(v.x, v.y);
            __half2 p1 = __floats2half2_rn(v.z, v.w);
            uint32_t addr = sb + OFF_B + sw_off(n, k);
            asm volatile("st.shared.v2.b32 [%0], {%1,%2};"
                         :: "r"(addr), "r"(*(uint32_t*)&p0), "r"(*(uint32_t*)&p1));
        }
    }
    if (tid < 256) csh[tid] = bias[tid] - sub[tid] - LSE_OFF;
    __syncthreads();   // B + csh visible; quarters never full-sync again

    const int t0 = 4 * blockIdx.x + q;

    // ---- per-quarter prologue: load + convert + stage x(t0); keep fp16 in regs ----
    uint32_t h2[32];
    {
        const float4* xp = (const float4*)(x + (size_t)t0 * (32 * KDIM));
#pragma unroll
        for (int i = 0; i < 16; i++) {
            float4 v = __ldcs(xp + i * 128 + tidq);
            __half2 a = __floats2half2_rn(v.x, v.y);
            __half2 b = __floats2half2_rn(v.z, v.w);
            h2[2 * i] = *(uint32_t*)&a;
            h2[2 * i + 1] = *(uint32_t*)&b;
        }
#pragma unroll
        for (int i = 0; i < 16; i++) {
            int e = i * 512 + tidq * 4;
            uint32_t addr = aQ + sw_off(e >> 8, e & 255);
            asm volatile("st.shared.v2.b32 [%0], {%1,%2};"
                         :: "r"(addr), "r"(h2[2 * i]), "r"(h2[2 * i + 1]));
        }
    }
    BARQ(barid);

    // ---- ldmatrix lane addresses (k-invariant parts) ----
    const int t4 = lane >> 3;
    const int a_row = (t4 & 1) * 8 + (lane & 7);
    const uint32_t a_kh = (uint32_t)(t4 >> 1);
    const int b_row0 = nw * 64 + (t4 >> 1) * 8 + (lane & 7);
    const uint32_t b_kh = (uint32_t)(t4 & 1);
    const uint32_t aBase0 = aQ + (uint32_t)(a_row * 512);
    const uint32_t aBase1 = aBase0 + 16 * 512;
    const uint32_t aRx = (uint32_t)(a_row & 7);
    uint32_t bBase[4], bRx[4];
#pragma unroll
    for (int ng = 0; ng < 4; ng++) {
        int br = b_row0 + ng * 16;
        bBase[ng] = sb + OFF_B + (uint32_t)(br * 512);
        bRx[ng] = (uint32_t)(br & 7);
    }

    for (int t = t0; t < NT; t += 4 * GRIDSZ) {
        // A(t) staged & visible (barrier at loop end / prologue)

        float acc[64];
#pragma unroll
        for (int i = 0; i < 64; i++) acc[i] = 0.0f;

        // ---- MMA mainloop: 16 k-steps of k16; warp = 32 rows x 64 cols ----
#pragma unroll
        for (int ks = 0; ks < 16; ks++) {
            const uint32_t kc = (uint32_t)(2 * ks);
            uint32_t a0[4], a1[4];
            LDSM_X4(a0[0], a0[1], a0[2], a0[3], aBase0 + (((kc + a_kh) ^ aRx) << 4));
            LDSM_X4(a1[0], a1[1], a1[2], a1[3], aBase1 + (((kc + a_kh) ^ aRx) << 4));
            uint32_t bf[4][4];
#pragma unroll
            for (int ng = 0; ng < 4; ng++)
                LDSM_X4(bf[ng][0], bf[ng][1], bf[ng][2], bf[ng][3],
                        bBase[ng] + (((kc + b_kh) ^ bRx[ng]) << 4));
#pragma unroll
            for (int ng = 0; ng < 4; ng++) {
                MMA16816(&acc[(ng * 2 + 0) * 4], a0, bf[ng][0], bf[ng][1]);
                MMA16816(&acc[(ng * 2 + 1) * 4], a0, bf[ng][2], bf[ng][3]);
                MMA16816(&acc[(8 + ng * 2 + 0) * 4], a1, bf[ng][0], bf[ng][1]);
                MMA16816(&acc[(8 + ng * 2 + 1) * 4], a1, bf[ng][2], bf[ng][3]);
            }
        }

        // ---- epilogue: no-max LSE partial sums (bias-sub-44 folded into csh) ----
        {
            const int n0 = nw * 64;
            float s4[4] = {0.0f, 0.0f, 0.0f, 0.0f};
#pragma unroll
            for (int nt = 0; nt < 8; nt++) {
                float c0 = csh[n0 + nt * 8 + (lane & 3) * 2];
                float c1 = csh[n0 + nt * 8 + (lane & 3) * 2 + 1];
#pragma unroll
                for (int mb = 0; mb < 2; mb++) {
                    const float* a = &acc[(mb * 8 + nt) * 4];
                    s4[2 * mb + 0] += __expf(a[0] + c0) + __expf(a[1] + c1);
                    s4[2 * mb + 1] += __expf(a[2] + c0) + __expf(a[3] + c1);
                }
            }
#pragma unroll
            for (int off = 1; off <= 2; off <<= 1) {
#pragma unroll
                for (int j = 0; j < 4; j++)
                    s4[j] += __shfl_xor_sync(0xFFFFFFFFu, s4[j], off);
            }
            if ((lane & 3) == 0) {
#pragma unroll
                for (int j = 0; j < 4; j++) {
                    int row = (j >> 1) * 16 + (j & 1) * 8 + (lane >> 2);
                    psumQ[nw * 32 + row] = s4[j];
                }
            }
        }
        BARQ(barid);   // psum visible; all LDSM of A(t) done

        // ---- combine 4 N-group partials -> lse -> gelu ----
        if (tidq < 32) {
            float S = psumQ[tidq] + psumQ[32 + tidq] + psumQ[64 + tidq] + psumQ[96 + tidq];
            float l = __logf(S) + LSE_OFF;
            float u = 0.7978845608028654f * (l + 0.044715f * l * l * l);
            gshQ[tidq] = 0.5f * l * (1.0f + tanhf(u));
        }
        BARQ(barid);   // gsh visible

        // ---- store out(t) = gelu(lse) + x(t), residual straight from registers ----
        {
            float* op = out + (size_t)t * (32 * KDIM);
#pragma unroll
            for (int i = 0; i < 16; i++) {
                int e = i * 512 + tidq * 4;
                float gv = gshQ[e >> 8];
                __half2 p0 = *(__half2*)&h2[2 * i];
                __half2 p1 = *(__half2*)&h2[2 * i + 1];
                float4 o;
                o.x = __low2float(p0) + gv;
                o.y = __high2float(p0) + gv;
                o.z = __low2float(p1) + gv;
                o.w = __high2float(p1) + gv;
                __stcs((float4*)(op + e), o);
            }
        }

        // ---- load + convert + stage x(t+1) (covered by other quarters' MMA) ----
        const int tn = t + 4 * GRIDSZ;
        if (tn < NT) {
            const float4* xp = (const float4*)(x + (size_t)tn * (32 * KDIM));
#pragma unroll
            for (int i = 0; i < 16; i++) {
                float4 v = __ldcs(xp + i * 128 + tidq);
                __half2 a = __floats2half2_rn(v.x, v.y);
                __half2 b = __floats2half2_rn(v.z, v.w);
                h2[2 * i] = *(uint32_t*)&a;
                h2[2 * i + 1] = *(uint32_t*)&b;
            }
#pragma unroll
            for (int i = 0; i < 16; i++) {
                int e = i * 512 + tidq * 4;
                uint32_t addr = aQ + sw_off(e >> 8, e & 255);
                asm volatile("st.shared.v2.b32 [%0], {%1,%2};"
                             :: "r"(addr), "r"(h2[2 * i]), "r"(h2[2 * i + 1]));
            }
        }
        BARQ(barid);   // A(t+1) visible for next MMA
    }
}

extern "C" void kernel_launch(void* const* d_in, const int* in_sizes, int n_in,
                              void* d_out, int out_size) {
    const float* x    = (const float*)d_in[0];
    const float* w    = (const float*)d_in[1];
    const float* bias = (const float*)d_in[2];
    const float* sub  = (const float*)d_in[3];
    float* out = (float*)d_out;

    cudaFuncSetAttribute(fused_gemm_lse_gelu_kernel,
                         cudaFuncAttributeMaxDynamicSharedMemorySize, SMEM_TOTAL);
    fused_gemm_lse_gelu_kernel<<<GRIDSZ, THREADS, SMEM_TOTAL>>>(x, w, bias, sub, out);
}

// round 15
// speedup vs baseline: 1.5183x; 1.1268x over previous
#include <cuda_runtime.h>
#include <cuda_fp16.h>
#include <cstdint>

#define NT        32768     // M / 16-row tiles
#define GRIDSZ    148
#define THREADS   768
#define NPIPE     6
#define KDIM      256
#define NDIM      256
#define LSE_OFF   44.0f

// ---- dynamic smem layout (bytes) ----
#define OFF_C     0                    // 256 fp32 (bias - subtract - LSE_OFF)
#define OFF_PSUM  1024                 // 6 pipes x (4 x 16) fp32 = 1536
#define OFF_G     2560                 // 6 pipes x 16 fp32 = 384
#define OFF_A     4096                 // 6 pipes x (16 x 256 fp16 = 8192)
#define OFF_B     53248                // 256 x 256 fp16 = 131072
#define SMEM_TOTAL 184320

__device__ __forceinline__ uint32_t cvta_smem(const void* p) {
    uint32_t a;
    asm("{ .reg .u64 t; cvta.to.shared.u64 t, %1; cvt.u32.u64 %0, t; }" : "=r"(a) : "l"(p));
    return a;
}

// Swizzle<3,3,3>: row stride 512B (256 fp16). 16B-chunk index ^= row&7.
__device__ __forceinline__ uint32_t sw_off(int row, int col) {
    return (uint32_t)(row * 512 + (((col >> 3) ^ (row & 7)) << 4) + (col & 7) * 2);
}

#define LDSM_X4(r0, r1, r2, r3, addr) \
    asm volatile("ldmatrix.sync.aligned.m8n8.x4.shared.b16 {%0,%1,%2,%3}, [%4];" \
                 : "=r"(r0), "=r"(r1), "=r"(r2), "=r"(r3) : "r"(addr))

#define MMA16816(d, a, b0, b1) \
    asm volatile("mma.sync.aligned.m16n8k16.row.col.f32.f16.f16.f32 " \
                 "{%0,%1,%2,%3}, {%4,%5,%6,%7}, {%8,%9}, {%0,%1,%2,%3};" \
                 : "+f"((d)[0]), "+f"((d)[1]), "+f"((d)[2]), "+f"((d)[3]) \
                 : "r"((a)[0]), "r"((a)[1]), "r"((a)[2]), "r"((a)[3]), \
                   "r"(b0), "r"(b1))

// per-pipeline named barrier (128 threads each; ids 1..6)
#define BARQ(id) asm volatile("bar.sync %0, 128;" :: "r"(id) : "memory")

__global__ void __launch_bounds__(THREADS, 1)
fused_gemm_lse_gelu_kernel(const float* __restrict__ x,
                           const float* __restrict__ w,
                           const float* __restrict__ bias,
                           const float* __restrict__ sub,
                           float* __restrict__ out) {
    extern __shared__ char sm[];
    const uint32_t sb = cvta_smem(sm);
    const int tid  = threadIdx.x;
    const int lane = tid & 31;
    const int p    = tid >> 7;          // pipeline 0..5: independent 4-warp pipeline
    const int tidp = tid & 127;
    const int nw   = (tid >> 5) & 3;    // warp-in-pipeline: N-group cols nw*64..+63
    const int barid = p + 1;

    float* csh   = (float*)(sm + OFF_C);
    float* psumP = (float*)(sm + OFF_PSUM + p * 256);   // [4 groups][16 rows]
    float* gshP  = (float*)(sm + OFF_G + p * 64);       // [16 rows]
    const uint32_t aP = sb + OFF_A + (uint32_t)(p * 8192);

    // ---- stage W fp32 -> fp16 swizzled SMEM (512 threads; resident forever) ----
    if (tid < 512) {
        const float4* wp = (const float4*)w;
#pragma unroll
        for (int i = 0; i < 32; i++) {
            int e = i * 2048 + tid * 4;
            float4 v = wp[i * 512 + tid];
            int n = e >> 8, k = e & 255;
            __half2 p0 = __floats2half2_rn(v.x, v.y);
            __half2 p1 = __floats2half2_rn(v.z, v.w);
            uint32_t addr = sb + OFF_B + sw_off(n, k);
            asm volatile("st.shared.v2.b32 [%0], {%1,%2};"
                         :: "r"(addr), "r"(*(uint32_t*)&p0), "r"(*(uint32_t*)&p1));
        }
    }
    if (tid < 256) csh[tid] = bias[tid] - sub[tid] - LSE_OFF;
    __syncthreads();   // B + csh visible; pipelines never full-sync again

    const int t0 = NPIPE * blockIdx.x + p;

    // ---- per-pipeline prologue: load + convert + stage x(t0) ----
    {
        const float4* xp = (const float4*)(x + (size_t)t0 * (16 * KDIM));
#pragma unroll
        for (int i = 0; i < 8; i++) {
            float4 v = __ldcs(xp + i * 128 + tidp);
            __half2 a = __floats2half2_rn(v.x, v.y);
            __half2 b = __floats2half2_rn(v.z, v.w);
            int e = i * 512 + tidp * 4;
            uint32_t addr = aP + sw_off(e >> 8, e & 255);
            asm volatile("st.shared.v2.b32 [%0], {%1,%2};"
                         :: "r"(addr), "r"(*(uint32_t*)&a), "r"(*(uint32_t*)&b));
        }
    }
    BARQ(barid);

    // ---- ldmatrix lane addresses (k-invariant parts) ----
    const int t4 = lane >> 3;
    const int a_row = (t4 & 1) * 8 + (lane & 7);          // rows 0..15
    const uint32_t a_kh = (uint32_t)(t4 >> 1);
    const int b_row0 = nw * 64 + (t4 >> 1) * 8 + (lane & 7);
    const uint32_t b_kh = (uint32_t)(t4 & 1);
    const uint32_t aBase = aP + (uint32_t)(a_row * 512);
    const uint32_t aRx = (uint32_t)(a_row & 7);
    uint32_t bBase[4], bRx[4];
#pragma unroll
    for (int ng = 0; ng < 4; ng++) {
        int br = b_row0 + ng * 16;
        bBase[ng] = sb + OFF_B + (uint32_t)(br * 512);
        bRx[ng] = (uint32_t)(br & 7);
    }

    for (int t = t0; t < NT; t += NPIPE * GRIDSZ) {
        // A(t) staged & visible (barrier at loop end / prologue)

        float acc[32];
#pragma unroll
        for (int i = 0; i < 32; i++) acc[i] = 0.0f;

        // ---- MMA mainloop: 16 k-steps of k16; warp = 16 rows x 64 cols ----
#pragma unroll
        for (int ks = 0; ks < 16; ks++) {
            const uint32_t kc = (uint32_t)(2 * ks);
            uint32_t a0[4];
            LDSM_X4(a0[0], a0[1], a0[2], a0[3], aBase + (((kc + a_kh) ^ aRx) << 4));
            {
                uint32_t bf0[4], bf1[4];
                LDSM_X4(bf0[0], bf0[1], bf0[2], bf0[3],
                        bBase[0] + (((kc + b_kh) ^ bRx[0]) << 4));
                LDSM_X4(bf1[0], bf1[1], bf1[2], bf1[3],
                        bBase[1] + (((kc + b_kh) ^ bRx[1]) << 4));
                MMA16816(&acc[0],  a0, bf0[0], bf0[1]);
                MMA16816(&acc[4],  a0, bf0[2], bf0[3]);
                MMA16816(&acc[8],  a0, bf1[0], bf1[1]);
                MMA16816(&acc[12], a0, bf1[2], bf1[3]);
            }
            {
                uint32_t bf2[4], bf3[4];
                LDSM_X4(bf2[0], bf2[1], bf2[2], bf2[3],
                        bBase[2] + (((kc + b_kh) ^ bRx[2]) << 4));
                LDSM_X4(bf3[0], bf3[1], bf3[2], bf3[3],
                        bBase[3] + (((kc + b_kh) ^ bRx[3]) << 4));
                MMA16816(&acc[16], a0, bf2[0], bf2[1]);
                MMA16816(&acc[20], a0, bf2[2], bf2[3]);
                MMA16816(&acc[24], a0, bf3[0], bf3[1]);
                MMA16816(&acc[28], a0, bf3[2], bf3[3]);
            }
        }

        // ---- epilogue: no-max LSE partial sums (bias-sub-44 folded into csh) ----
        // acc[nt*4 + j]: cols nw*64 + nt*8 + (lane&3)*2 + (j&1); rows (lane>>2) + (j>>1)*8
        {
            const int n0 = nw * 64;
            float s2[2] = {0.0f, 0.0f};
#pragma unroll
            for (int nt = 0; nt < 8; nt++) {
                float c0 = csh[n0 + nt * 8 + (lane & 3) * 2];
                float c1 = csh[n0 + nt * 8 + (lane & 3) * 2 + 1];
                const float* a = &acc[nt * 4];
                s2[0] += __expf(a[0] + c0) + __expf(a[1] + c1);
                s2[1] += __expf(a[2] + c0) + __expf(a[3] + c1);
            }
#pragma unroll
            for (int off = 1; off <= 2; off <<= 1) {
                s2[0] += __shfl_xor_sync(0xFFFFFFFFu, s2[0], off);
                s2[1] += __shfl_xor_sync(0xFFFFFFFFu, s2[1], off);
            }
            if ((lane & 3) == 0) {
                int r = lane >> 2;
                psumP[nw * 16 + r] = s2[0];
                psumP[nw * 16 + r + 8] = s2[1];
            }
        }
        BARQ(barid);   // psum visible; all LDSM of A(t) done

        // ---- combine 4 N-group partials -> lse -> gelu (distributed 4 warps) ----
        if (lane < 4) {
            int row = nw * 4 + lane;
            float S = psumP[row] + psumP[16 + row] + psumP[32 + row] + psumP[48 + row];
            float l = __logf(S) + LSE_OFF;
            float u = 0.7978845608028654f * (l + 0.044715f * l * l * l);
            gshP[row] = 0.5f * l * (1.0f + tanhf(u));
        }
        BARQ(barid);   // gsh visible

        // ---- store out(t) = gelu(lse) + x(t); residual from fp16 A tile ----
        {
            float* op = out + (size_t)t * (16 * KDIM);
#pragma unroll
            for (int i = 0; i < 8; i++) {
                int e = i * 512 + tidp * 4;
                int r = e >> 8;
                uint32_t addr = aP + sw_off(r, e & 255);
                uint32_t u0, u1;
                asm volatile("ld.shared.v2.b32 {%0,%1}, [%2];" : "=r"(u0), "=r"(u1) : "r"(addr));
                __half2 p0 = *(__half2*)&u0;
                __half2 p1 = *(__half2*)&u1;
                float gv = gshP[r];
                float4 o;
                o.x = __low2float(p0) + gv;
                o.y = __high2float(p0) + gv;
                o.z = __low2float(p1) + gv;
                o.w = __high2float(p1) + gv;
                __stcs((float4*)(op + e), o);
            }
        }

        // ---- load + convert + stage x(t+1); same-thread bytes, no extra barrier ----
        const int tn = t + NPIPE * GRIDSZ;
        if (tn < NT) {
            const float4* xp = (const float4*)(x + (size_t)tn * (16 * KDIM));
#pragma unroll
            for (int i = 0; i < 8; i++) {
                float4 v = __ldcs(xp + i * 128 + tidp);
                __half2 a = __floats2half2_rn(v.x, v.y);
                __half2 b = __floats2half2_rn(v.z, v.w);
                int e = i * 512 + tidp * 4;
                uint32_t addr = aP + sw_off(e >> 8, e & 255);
                asm volatile("st.shared.v2.b32 [%0], {%1,%2};"
                             :: "r"(addr), "r"(*(uint32_t*)&a), "r"(*(uint32_t*)&b));
            }
        }
        BARQ(barid);   // A(t+1) visible for next MMA
    }
}

extern "C" void kernel_launch(void* const* d_in, const int* in_sizes, int n_in,
                              void* d_out, int out_size) {
    const float* x    = (const float*)d_in[0];
    const float* w    = (const float*)d_in[1];
    const float* bias = (const float*)d_in[2];
    const float* sub  = (const float*)d_in[3];
    float* out = (float*)d_out;

    cudaFuncSetAttribute(fused_gemm_lse_gelu_kernel,
                         cudaFuncAttributeMaxDynamicSharedMemorySize, SMEM_TOTAL);
    fused_gemm_lse_gelu_kernel<<<GRIDSZ, THREADS, SMEM_TOTAL>>>(x, w, bias, sub, out);
}

// round 17
// speedup vs baseline: 1.5785x; 1.0397x over previous
#include <cuda_runtime.h>
#include <cuda_fp16.h>
#include <cstdint>

#define NT        16384     // M / 32-row tiles
#define GRIDSZ    148
#define THREADS   768
#define NPIPE     3
#define KDIM      256
#define NDIM      256
#define LSE_OFF   44.0f

// ---- dynamic smem layout (bytes) ----
#define OFF_C     0                    // 256 fp32 (bias - subtract - LSE_OFF)
#define OFF_PSUM  1024                 // 3 pipes x (8 x 32) fp32 = 3072
#define OFF_G     4096                 // 3 pipes x 32 fp32 = 384
#define OFF_A     5120                 // 3 pipes x (32 x 256 fp16 = 16384)
#define OFF_B     54272                // 256 x 256 fp16 = 131072
#define SMEM_TOTAL 185344

__device__ __forceinline__ uint32_t cvta_smem(const void* p) {
    uint32_t a;
    asm("{ .reg .u64 t; cvta.to.shared.u64 t, %1; cvt.u32.u64 %0, t; }" : "=r"(a) : "l"(p));
    return a;
}

// Swizzle<3,3,3>: row stride 512B (256 fp16). 16B-chunk index ^= row&7.
__device__ __forceinline__ uint32_t sw_off(int row, int col) {
    return (uint32_t)(row * 512 + (((col >> 3) ^ (row & 7)) << 4) + (col & 7) * 2);
}

#define LDSM_X4(r0, r1, r2, r3, addr) \
    asm volatile("ldmatrix.sync.aligned.m8n8.x4.shared.b16 {%0,%1,%2,%3}, [%4];" \
                 : "=r"(r0), "=r"(r1), "=r"(r2), "=r"(r3) : "r"(addr))

#define MMA16816(d, a, b0, b1) \
    asm volatile("mma.sync.aligned.m16n8k16.row.col.f32.f16.f16.f32 " \
                 "{%0,%1,%2,%3}, {%4,%5,%6,%7}, {%8,%9}, {%0,%1,%2,%3};" \
                 : "+f"((d)[0]), "+f"((d)[1]), "+f"((d)[2]), "+f"((d)[3]) \
                 : "r"((a)[0]), "r"((a)[1]), "r"((a)[2]), "r"((a)[3]), \
                   "r"(b0), "r"(b1))

// per-pipeline named barrier (256 threads each; ids 1..3)
#define BARQ(id) asm volatile("bar.sync %0, 256;" :: "r"(id) : "memory")

__global__ void __launch_bounds__(THREADS, 1)
fused_gemm_lse_gelu_kernel(const float* __restrict__ x,
                           const float* __restrict__ w,
                           const float* __restrict__ bias,
                           const float* __restrict__ sub,
                           float* __restrict__ out) {
    extern __shared__ char sm[];
    const uint32_t sb = cvta_smem(sm);
    const int tid  = threadIdx.x;
    const int lane = tid & 31;
    const int p    = tid >> 8;          // pipeline 0..2: independent 8-warp pipeline
    const int tidp = tid & 255;
    const int nw   = (tid >> 5) & 7;    // warp-in-pipeline: N-group cols nw*32..+31
    const int barid = p + 1;

    float* csh   = (float*)(sm + OFF_C);
    float* psumP = (float*)(sm + OFF_PSUM + p * 1024);  // [8 groups][32 rows]
    float* gshP  = (float*)(sm + OFF_G + p * 128);      // [32 rows]
    const uint32_t aP = sb + OFF_A + (uint32_t)(p * 16384);

    // ---- stage W fp32 -> fp16 swizzled SMEM (512 threads; resident forever) ----
    if (tid < 512) {
        const float4* wp = (const float4*)w;
#pragma unroll
        for (int i = 0; i < 32; i++) {
            int e = i * 2048 + tid * 4;
            float4 v = wp[i * 512 + tid];
            int n = e >> 8, k = e & 255;
            __half2 p0 = __floats2half2_rn(v.x, v.y);
            __half2 p1 = __floats2half2_rn(v.z, v.w);
            uint32_t addr = sb + OFF_B + sw_off(n, k);
            asm volatile("st.shared.v2.b32 [%0], {%1,%2};"
                         :: "r"(addr), "r"(*(uint32_t*)&p0), "r"(*(uint32_t*)&p1));
        }
    }
    if (tid < 256) csh[tid] = bias[tid] - sub[tid] - LSE_OFF;
    __syncthreads();   // B + csh visible; pipelines never full-sync again

    const int t0 = NPIPE * blockIdx.x + p;

    // ---- per-pipeline prologue: load + convert + stage x(t0) ----
    {
        const float4* xp = (const float4*)(x + (size_t)t0 * (32 * KDIM));
#pragma unroll
        for (int i = 0; i < 8; i++) {
            float4 v = __ldcs(xp + i * 256 + tidp);
            __half2 a = __floats2half2_rn(v.x, v.y);
            __half2 b = __floats2half2_rn(v.z, v.w);
            int e = i * 1024 + tidp * 4;
            uint32_t addr = aP + sw_off(e >> 8, e & 255);
            asm volatile("st.shared.v2.b32 [%0], {%1,%2};"
                         :: "r"(addr), "r"(*(uint32_t*)&a), "r"(*(uint32_t*)&b));
        }
    }
    BARQ(barid);

    // ---- ldmatrix lane addresses (k-invariant parts) ----
    const int t4 = lane >> 3;
    const int a_row = (t4 & 1) * 8 + (lane & 7);          // rows 0..15 (a0), +16 (a1)
    const uint32_t a_kh = (uint32_t)(t4 >> 1);
    const int b_row0 = nw * 32 + (t4 >> 1) * 8 + (lane & 7);
    const uint32_t b_kh = (uint32_t)(t4 & 1);
    const uint32_t aBase0 = aP + (uint32_t)(a_row * 512);
    const uint32_t aBase1 = aBase0 + 16 * 512;
    const uint32_t aRx = (uint32_t)(a_row & 7);
    const uint32_t bBase0 = sb + OFF_B + (uint32_t)(b_row0 * 512);
    const uint32_t bBase1 = bBase0 + 16 * 512;
    const uint32_t bRx = (uint32_t)(b_row0 & 7);

    for (int t = t0; t < NT; t += NPIPE * GRIDSZ) {
        // A(t) staged & visible (barrier at loop end / prologue)

        float acc[32];
#pragma unroll
        for (int i = 0; i < 32; i++) acc[i] = 0.0f;

        // ---- MMA mainloop: 16 k-steps of k16; warp = 32 rows x 32 cols ----
        //      4 ldsm.x4 per k-step (2 A + 2 B): best smem-bytes/output at 32 acc
#pragma unroll
        for (int ks = 0; ks < 16; ks++) {
            const uint32_t kc = (uint32_t)(2 * ks);
            uint32_t a0[4], a1[4], bf0[4], bf1[4];
            LDSM_X4(a0[0], a0[1], a0[2], a0[3], aBase0 + (((kc + a_kh) ^ aRx) << 4));
            LDSM_X4(a1[0], a1[1], a1[2], a1[3], aBase1 + (((kc + a_kh) ^ aRx) << 4));
            LDSM_X4(bf0[0], bf0[1], bf0[2], bf0[3], bBase0 + (((kc + b_kh) ^ bRx) << 4));
            LDSM_X4(bf1[0], bf1[1], bf1[2], bf1[3], bBase1 + (((kc + b_kh) ^ bRx) << 4));
            MMA16816(&acc[0],  a0, bf0[0], bf0[1]);
            MMA16816(&acc[4],  a0, bf0[2], bf0[3]);
            MMA16816(&acc[8],  a0, bf1[0], bf1[1]);
            MMA16816(&acc[12], a0, bf1[2], bf1[3]);
            MMA16816(&acc[16], a1, bf0[0], bf0[1]);
            MMA16816(&acc[20], a1, bf0[2], bf0[3]);
            MMA16816(&acc[24], a1, bf1[0], bf1[1]);
            MMA16816(&acc[28], a1, bf1[2], bf1[3]);
        }

        // ---- epilogue: no-max LSE partial sums over this warp's 32 cols ----
        // acc[mb*16 + nt*4 + j]: rows mb*16 + (j>>1)*8 + (lane>>2),
        //                        cols nw*32 + nt*8 + (lane&3)*2 + (j&1)
        {
            const int n0 = nw * 32;
            float s4[4] = {0.0f, 0.0f, 0.0f, 0.0f};
#pragma unroll
            for (int nt = 0; nt < 4; nt++) {
                float c0 = csh[n0 + nt * 8 + (lane & 3) * 2];
                float c1 = csh[n0 + nt * 8 + (lane & 3) * 2 + 1];
#pragma unroll
                for (int mb = 0; mb < 2; mb++) {
                    const float* a = &acc[mb * 16 + nt * 4];
                    s4[2 * mb + 0] += __expf(a[0] + c0) + __expf(a[1] + c1);
                    s4[2 * mb + 1] += __expf(a[2] + c0) + __expf(a[3] + c1);
                }
            }
#pragma unroll
            for (int off = 1; off <= 2; off <<= 1) {
#pragma unroll
                for (int j = 0; j < 4; j++)
                    s4[j] += __shfl_xor_sync(0xFFFFFFFFu, s4[j], off);
            }
            if ((lane & 3) == 0) {
#pragma unroll
                for (int j = 0; j < 4; j++) {
                    int row = (j >> 1) * 16 + (j & 1) * 8 + (lane >> 2);
                    psumP[nw * 32 + row] = s4[j];
                }
            }
        }
        BARQ(barid);   // psum visible; all LDSM of A(t) done

        // ---- combine 8 N-group partials -> lse -> gelu (8 warps x 4 rows) ----
        if (lane < 4) {
            int row = nw * 4 + lane;
            float S = 0.0f;
#pragma unroll
            for (int ng = 0; ng < 8; ng++) S += psumP[ng * 32 + row];
            float l = __logf(S) + LSE_OFF;
            float u = 0.7978845608028654f * (l + 0.044715f * l * l * l);
            gshP[row] = 0.5f * l * (1.0f + tanhf(u));
        }
        BARQ(barid);   // gsh visible

        // ---- store out(t) = gelu(lse) + x(t); residual from fp16 A tile ----
        {
            float* op = out + (size_t)t * (32 * KDIM);
#pragma unroll
            for (int i = 0; i < 8; i++) {
                int e = i * 1024 + tidp * 4;
                int r = e >> 8;
                uint32_t addr = aP + sw_off(r, e & 255);
                uint32_t u0, u1;
                asm volatile("ld.shared.v2.b32 {%0,%1}, [%2];" : "=r"(u0), "=r"(u1) : "r"(addr));
                __half2 p0 = *(__half2*)&u0;
                __half2 p1 = *(__half2*)&u1;
                float gv = gshP[r];
                float4 o;
                o.x = __low2float(p0) + gv;
                o.y = __high2float(p0) + gv;
                o.z = __low2float(p1) + gv;
                o.w = __high2float(p1) + gv;
                __stcs((float4*)(op + e), o);
            }
        }

        // ---- load + convert + stage x(t+1); same-thread bytes, no extra barrier ----
        const int tn = t + NPIPE * GRIDSZ;
        if (tn < NT) {
            const float4* xp = (const float4*)(x + (size_t)tn * (32 * KDIM));
#pragma unroll
            for (int i = 0; i < 8; i++) {
                float4 v = __ldcs(xp + i * 256 + tidp);
                __half2 a = __floats2half2_rn(v.x, v.y);
                __half2 b = __floats2half2_rn(v.z, v.w);
                int e = i * 1024 + tidp * 4;
                uint32_t addr = aP + sw_off(e >> 8, e & 255);
                asm volatile("st.shared.v2.b32 [%0], {%1,%2};"
                             :: "r"(addr), "r"(*(uint32_t*)&a), "r"(*(uint32_t*)&b));
            }
        }
        BARQ(barid);   // A(t+1) visible for next MMA
    }
}

extern "C" void kernel_launch(void* const* d_in, const int* in_sizes, int n_in,
                              void* d_out, int out_size) {
    const float* x    = (const float*)d_in[0];
    const float* w    = (const float*)d_in[1];
    const float* bias = (const float*)d_in[2];
    const float* sub  = (const float*)d_in[3];
    float* out = (float*)d_out;

    cudaFuncSetAttribute(fused_gemm_lse_gelu_kernel,
                         cudaFuncAttributeMaxDynamicSharedMemorySize, SMEM_TOTAL);
    fused_gemm_lse_gelu_kernel<<<GRIDSZ, THREADS, SMEM_TOTAL>>>(x, w, bias, sub, out);
}